// round 1
// baseline (speedup 1.0000x reference)
#include <cuda_runtime.h>
#include <math.h>

// ---------------- problem constants ----------------
// B=2, S=2048, H=1024, E=8, K=2, capacity = int(2*2048*1.5*2/8) = 1536
#define TOKENS      4096            // B*S
#define HID         1024
#define NEXP        8
#define CAP         1536
#define NSLOTS      8192            // TOKENS*K
#define DISP_ELEMS  50331648L       // 4096*8*1536
#define ZERO_ELEMS  100663296L      // 2*DISP_ELEMS
#define PROBS_OFF   100663296L
#define AUX_OFF     100696064L      // PROBS_OFF + 4096*8

// ---------------- device scratch (no cudaMalloc allowed) ----------------
__device__ float g_avgp[2 * 16 * 1024];
__device__ float g_avg[2 * 1024];
__device__ float g_hc[2 * 1024];
__device__ float g_adj[16];
__device__ float g_hidden2[TOKENS * HID];   // 16 MB relu(X@w1+b1)
__device__ int   g_topk_e[NSLOTS];
__device__ float g_topk_p[NSLOTS];

// ================= K1a/K1b: avg_features = mean over S =================
__global__ void k_avg1(const float* __restrict__ hs)
{
    int b = blockIdx.x, c = blockIdx.y, h = threadIdx.x;
    const float* p = hs + (long)b * 2048 * 1024 + (long)c * 128 * 1024 + h;
    float s = 0.f;
    #pragma unroll 4
    for (int t = 0; t < 128; t++) s += p[(long)t * 1024];
    g_avgp[(b * 16 + c) * 1024 + h] = s;
}

__global__ void k_avg2()
{
    int b = blockIdx.x, h = threadIdx.x;
    float s = 0.f;
    #pragma unroll
    for (int c = 0; c < 16; c++) s += g_avgp[(b * 16 + c) * 1024 + h];
    g_avg[b * 1024 + h] = s * (1.f / 2048.f);
}

// ========== K2a: hc = relu([avg, cache] @ wc1 + bc1)  grid(2,8)x128 ==========
__global__ void k_cache1(const float* __restrict__ wc1,
                         const float* __restrict__ bc1,
                         const float* __restrict__ cache)
{
    __shared__ float comb[1032];
    int b = blockIdx.x, r = blockIdx.y;
    for (int i = threadIdx.x; i < 1032; i += 128)
        comb[i] = (i < 1024) ? g_avg[b * 1024 + i] : cache[i - 1024];
    __syncthreads();
    int j = r * 128 + threadIdx.x;
    float acc = bc1[j];
    #pragma unroll 8
    for (int i = 0; i < 1032; i++) acc = fmaf(comb[i], wc1[(long)i * 1024 + j], acc);
    g_hc[b * 1024 + j] = fmaxf(acc, 0.f);
}

// ========== K2b: adj = tanh(hc @ wc2 + bc2)  grid 2 x 256 ==========
__global__ void k_cache2(const float* __restrict__ wc2,
                         const float* __restrict__ bc2)
{
    __shared__ float hc[1024];
    int b = blockIdx.x;
    for (int i = threadIdx.x; i < 1024; i += 256) hc[i] = g_hc[b * 1024 + i];
    __syncthreads();
    int e = threadIdx.x >> 5, lane = threadIdx.x & 31;
    float acc = 0.f;
    for (int i = lane; i < 1024; i += 32) acc = fmaf(hc[i], wc2[i * 8 + e], acc);
    #pragma unroll
    for (int off = 16; off > 0; off >>= 1)
        acc += __shfl_down_sync(0xffffffffu, acc, off);
    if (lane == 0) g_adj[b * 8 + e] = tanhf(acc + bc2[e]);
}

// ========== K3: hidden2 = relu(X @ w1 + b1) fp32 SGEMM + fused output zeroing ==========
// BM=128 BN=128 BK=16, 256 threads, 8x8 per thread, double-buffered smem, grid 256.
__global__ __launch_bounds__(256, 2)
void k_gemm1(const float* __restrict__ A, const float* __restrict__ W,
             const float* __restrict__ bias, float* __restrict__ zbase)
{
    // -------- fused zero-fill of dispatch+combine (402 MB), hides under FFMA mainloop --------
    {
        const long NV = ZERO_ELEMS / 4;
        uint4* p = reinterpret_cast<uint4*>(zbase);
        uint4 z; z.x = z.y = z.z = z.w = 0u;
        long stride = (long)gridDim.x * blockDim.x;
        for (long i = (long)blockIdx.x * blockDim.x + threadIdx.x; i < NV; i += stride)
            p[i] = z;
    }

    __shared__ float As[2][16][132];   // padded: conflict-reduced transpose stores
    __shared__ float Bs[2][16][128];

    const int tid = threadIdx.x;
    const int bx = blockIdx.x & 7;     // N tile (1024/128)
    const int by = blockIdx.x >> 3;    // M tile (4096/128)
    const int tx = tid & 15;
    const int ty = tid >> 4;

    const int arow = tid >> 2;         // 0..63
    const int ac4  = tid & 3;          // 0..3
    const int brow = tid >> 5;         // 0..7
    const int bc4  = tid & 31;         // 0..31

    const float* Ab = A + (long)by * 128 * 1024;
    const float* Wb = W + bx * 128;

    float acc[8][8];
    #pragma unroll
    for (int i = 0; i < 8; i++)
        #pragma unroll
        for (int j = 0; j < 8; j++) acc[i][j] = 0.f;

    float4 ra0, ra1, rb0, rb1;

    // prefetch tile 0
    ra0 = *(const float4*)(Ab + (long)arow * 1024 + ac4 * 4);
    ra1 = *(const float4*)(Ab + (long)(arow + 64) * 1024 + ac4 * 4);
    rb0 = *(const float4*)(Wb + (long)brow * 1024 + bc4 * 4);
    rb1 = *(const float4*)(Wb + (long)(brow + 8) * 1024 + bc4 * 4);

    As[0][ac4 * 4 + 0][arow] = ra0.x; As[0][ac4 * 4 + 1][arow] = ra0.y;
    As[0][ac4 * 4 + 2][arow] = ra0.z; As[0][ac4 * 4 + 3][arow] = ra0.w;
    As[0][ac4 * 4 + 0][arow + 64] = ra1.x; As[0][ac4 * 4 + 1][arow + 64] = ra1.y;
    As[0][ac4 * 4 + 2][arow + 64] = ra1.z; As[0][ac4 * 4 + 3][arow + 64] = ra1.w;
    *(float4*)&Bs[0][brow][bc4 * 4] = rb0;
    *(float4*)&Bs[0][brow + 8][bc4 * 4] = rb1;
    __syncthreads();

    for (int kt = 0; kt < 64; ++kt) {
        const int cur = kt & 1;
        if (kt < 63) {
            const float* Ak = Ab + (kt + 1) * 16;
            ra0 = *(const float4*)(Ak + (long)arow * 1024 + ac4 * 4);
            ra1 = *(const float4*)(Ak + (long)(arow + 64) * 1024 + ac4 * 4);
            const float* Wk = Wb + (long)((kt + 1) * 16) * 1024;
            rb0 = *(const float4*)(Wk + (long)brow * 1024 + bc4 * 4);
            rb1 = *(const float4*)(Wk + (long)(brow + 8) * 1024 + bc4 * 4);
        }
        #pragma unroll
        for (int kk = 0; kk < 16; kk++) {
            float af[8], bf[8];
            *(float4*)&af[0] = *(const float4*)&As[cur][kk][ty * 8];
            *(float4*)&af[4] = *(const float4*)&As[cur][kk][ty * 8 + 4];
            *(float4*)&bf[0] = *(const float4*)&Bs[cur][kk][tx * 8];
            *(float4*)&bf[4] = *(const float4*)&Bs[cur][kk][tx * 8 + 4];
            #pragma unroll
            for (int i = 0; i < 8; i++)
                #pragma unroll
                for (int j = 0; j < 8; j++)
                    acc[i][j] = fmaf(af[i], bf[j], acc[i][j]);
        }
        if (kt < 63) {
            const int nxt = cur ^ 1;
            As[nxt][ac4 * 4 + 0][arow] = ra0.x; As[nxt][ac4 * 4 + 1][arow] = ra0.y;
            As[nxt][ac4 * 4 + 2][arow] = ra0.z; As[nxt][ac4 * 4 + 3][arow] = ra0.w;
            As[nxt][ac4 * 4 + 0][arow + 64] = ra1.x; As[nxt][ac4 * 4 + 1][arow + 64] = ra1.y;
            As[nxt][ac4 * 4 + 2][arow + 64] = ra1.z; As[nxt][ac4 * 4 + 3][arow + 64] = ra1.w;
            *(float4*)&Bs[nxt][brow][bc4 * 4] = rb0;
            *(float4*)&Bs[nxt][brow + 8][bc4 * 4] = rb1;
            __syncthreads();
        }
    }

    // epilogue: + b1, relu, store
    float4 bv0 = *(const float4*)(bias + bx * 128 + tx * 8);
    float4 bv1 = *(const float4*)(bias + bx * 128 + tx * 8 + 4);
    #pragma unroll
    for (int i = 0; i < 8; i++) {
        long row = (long)by * 128 + ty * 8 + i;
        float* o = g_hidden2 + row * 1024 + bx * 128 + tx * 8;
        float4 v0, v1;
        v0.x = fmaxf(acc[i][0] + bv0.x, 0.f);
        v0.y = fmaxf(acc[i][1] + bv0.y, 0.f);
        v0.z = fmaxf(acc[i][2] + bv0.z, 0.f);
        v0.w = fmaxf(acc[i][3] + bv0.w, 0.f);
        v1.x = fmaxf(acc[i][4] + bv1.x, 0.f);
        v1.y = fmaxf(acc[i][5] + bv1.y, 0.f);
        v1.z = fmaxf(acc[i][6] + bv1.z, 0.f);
        v1.w = fmaxf(acc[i][7] + bv1.w, 0.f);
        *(float4*)o = v0;
        *(float4*)(o + 4) = v1;
    }
}

// ========== K4: logits = hidden2@w2 + b2 + adj; softmax; top-2  (warp/token) ==========
__global__ void k_logits(const float* __restrict__ w2,
                         const float* __restrict__ b2,
                         float* __restrict__ out)
{
    __shared__ float sw2[8 * 1024];
    __shared__ float sb2[8];
    __shared__ float sadj[16];
    for (int idx = threadIdx.x; idx < 8192; idx += 256) {
        int i = idx >> 3, e = idx & 7;
        sw2[e * 1024 + i] = w2[idx];
    }
    if (threadIdx.x < 8)  sb2[threadIdx.x]  = b2[threadIdx.x];
    if (threadIdx.x < 16) sadj[threadIdx.x] = g_adj[threadIdx.x];
    __syncthreads();

    int warp = threadIdx.x >> 5, lane = threadIdx.x & 31;
    int tok = blockIdx.x * 8 + warp;

    float acc[8] = {0, 0, 0, 0, 0, 0, 0, 0};
    const float* xr = g_hidden2 + (long)tok * 1024;
    #pragma unroll 4
    for (int t = 0; t < 32; t++) {
        int i = t * 32 + lane;
        float x = xr[i];
        #pragma unroll
        for (int e = 0; e < 8; e++) acc[e] = fmaf(x, sw2[e * 1024 + i], acc[e]);
    }
    #pragma unroll
    for (int e = 0; e < 8; e++)
        #pragma unroll
        for (int off = 16; off > 0; off >>= 1)
            acc[e] += __shfl_down_sync(0xffffffffu, acc[e], off);

    if (lane == 0) {
        int b = tok >> 11;
        float l[8], m = -1e30f;
        #pragma unroll
        for (int e = 0; e < 8; e++) {
            l[e] = acc[e] + sb2[e] + sadj[b * 8 + e];
            m = fmaxf(m, l[e]);
        }
        float p[8], s = 0.f;
        #pragma unroll
        for (int e = 0; e < 8; e++) { p[e] = expf(l[e] - m); s += p[e]; }
        float inv = 1.f / s;
        float* pr = out + PROBS_OFF + (long)tok * 8;
        #pragma unroll
        for (int e = 0; e < 8; e++) { p[e] *= inv; pr[e] = p[e]; }
        // top-2, lowest index wins ties (jax.lax.top_k semantics)
        int e1 = 0;
        #pragma unroll
        for (int e = 1; e < 8; e++) if (p[e] > p[e1]) e1 = e;
        int e2 = (e1 == 0) ? 1 : 0;
        #pragma unroll
        for (int e = 0; e < 8; e++) if (e != e1 && p[e] > p[e2]) e2 = e;
        float d = p[e1] + p[e2] + 1e-8f;
        g_topk_e[tok * 2]     = e1;
        g_topk_e[tok * 2 + 1] = e2;
        g_topk_p[tok * 2]     = p[e1] / d;
        g_topk_p[tok * 2 + 1] = p[e2] / d;
    }
}

// ========== K5: serial-order capacity scan + scatter + aux loss (1 block x 1024) ==========
__global__ void k_scan(float* __restrict__ out)
{
    __shared__ unsigned int ss[4 * 1024];  // 8 experts x 16-bit packed counters
    __shared__ float red[1024];
    __shared__ float psum[8];
    const int tid = threadIdx.x;

    // phase A: per-expert softmax-prob sums (deterministic tree)
    const float* pr = out + PROBS_OFF;
    float ps[8] = {0, 0, 0, 0, 0, 0, 0, 0};
    for (int tok = tid; tok < 4096; tok += 1024) {
        const float* r = pr + (long)tok * 8;
        #pragma unroll
        for (int e = 0; e < 8; e++) ps[e] += r[e];
    }
    for (int e = 0; e < 8; e++) {
        red[tid] = ps[e];
        __syncthreads();
        for (int off = 512; off > 0; off >>= 1) {
            if (tid < off) red[tid] += red[tid + off];
            __syncthreads();
        }
        if (tid == 0) psum[e] = red[0];
        __syncthreads();
    }

    // phase B: packed Hillis-Steele inclusive scan of per-expert counts over 8192 slots
    int myE[8]; float myP[8];
    unsigned int c[4] = {0, 0, 0, 0};
    #pragma unroll
    for (int j = 0; j < 8; j++) {
        int n = tid * 8 + j;
        int e = g_topk_e[n];
        myE[j] = e;
        myP[j] = g_topk_p[n];
        c[e >> 1] += 1u << ((e & 1) * 16);
    }
    #pragma unroll
    for (int w = 0; w < 4; w++) ss[w * 1024 + tid] = c[w];
    __syncthreads();
    for (int off = 1; off < 1024; off <<= 1) {
        unsigned int a[4] = {0, 0, 0, 0};
        if (tid >= off) {
            #pragma unroll
            for (int w = 0; w < 4; w++) a[w] = ss[w * 1024 + tid - off];
        }
        __syncthreads();
        if (tid >= off) {
            #pragma unroll
            for (int w = 0; w < 4; w++) ss[w * 1024 + tid] += a[w];
        }
        __syncthreads();
    }
    int run[8];
    #pragma unroll
    for (int w = 0; w < 4; w++) {
        unsigned int exc = ss[w * 1024 + tid] - c[w];  // exclusive prefix
        run[2 * w]     = (int)(exc & 0xffffu);
        run[2 * w + 1] = (int)(exc >> 16);
    }

    // phase C: scatter kept slots (zeros already written by k_gemm1)
    float* disp = out;
    float* comb = out + DISP_ELEMS;
    #pragma unroll
    for (int j = 0; j < 8; j++) {
        int n = tid * 8 + j;
        int e = myE[j];
        int pos = run[e]++;
        if (pos < CAP) {
            long tok = n >> 1;
            long o = tok * 12288L + (long)e * 1536L + pos;
            disp[o] = 1.0f;
            comb[o] = myP[j];
        }
    }

    // phase D: aux loss
    if (tid == 0) {
        float aux = 0.f;
        #pragma unroll
        for (int e = 0; e < 8; e++) {
            unsigned int inc = ss[(e >> 1) * 1024 + 1023];
            float cnt = (float)((inc >> ((e & 1) * 16)) & 0xffffu);
            aux += (psum[e] * (1.f / 4096.f)) * (cnt * (1.f / 8192.f));
        }
        out[AUX_OFF] = aux * 8.f;
    }
}

// ---------------- launch ----------------
extern "C" void kernel_launch(void* const* d_in, const int* in_sizes, int n_in,
                              void* d_out, int out_size)
{
    const float* hs    = (const float*)d_in[0];
    const float* w1    = (const float*)d_in[1];
    const float* b1    = (const float*)d_in[2];
    const float* w2    = (const float*)d_in[3];
    const float* b2    = (const float*)d_in[4];
    const float* wc1   = (const float*)d_in[5];
    const float* bc1   = (const float*)d_in[6];
    const float* wc2   = (const float*)d_in[7];
    const float* bc2   = (const float*)d_in[8];
    const float* cache = (const float*)d_in[9];
    float* out = (float*)d_out;

    k_avg1<<<dim3(2, 16), 1024>>>(hs);
    k_avg2<<<2, 1024>>>();
    k_cache1<<<dim3(2, 8), 128>>>(wc1, bc1, cache);
    k_cache2<<<2, 256>>>(wc2, bc2);
    k_gemm1<<<256, 256>>>(hs, w1, b1, out);
    k_logits<<<512, 256>>>(w2, b2, out);
    k_scan<<<1, 1024>>>(out);
}

// round 3
// speedup vs baseline: 1.9554x; 1.9554x over previous
#include <cuda_runtime.h>
#include <cuda_bf16.h>
#include <math.h>
#include <stdint.h>

// ---------------- problem constants ----------------
// B=2, S=2048, H=1024, E=8, K=2, capacity = int(2*2048*1.5*2/8) = 1536
#define TOKENS      4096
#define HID         1024
#define NEXP        8
#define CAP         1536
#define NSLOTS      8192
#define DISP_ELEMS  50331648L
#define ZERO_ELEMS  100663296L
#define PROBS_OFF   100663296L
#define AUX_OFF     100696064L

// ---------------- device scratch ----------------
__device__ __align__(128) __nv_bfloat16 g_Ahb[TOKENS * HID];
__device__ __align__(128) __nv_bfloat16 g_Alb[TOKENS * HID];
__device__ __align__(128) __nv_bfloat16 g_Bhb[HID * HID];   // w1^T: [n][k]
__device__ __align__(128) __nv_bfloat16 g_Blb[HID * HID];
__device__ __align__(128) float g_plog[32 * TOKENS * NEXP]; // partial logits
__device__ float g_avgp[2 * 64 * 1024];
__device__ float g_avg[2 * 1024];
__device__ float g_c1p[8 * 2 * 1024];
__device__ float g_hc[2 * 1024];
__device__ float g_adj[16];
__device__ float g_psum[32 * 8];
__device__ int   g_topk_e[NSLOTS];
__device__ float g_topk_p[NSLOTS];

// ---------------- PTX helpers (portable: sm_80+) ----------------
__device__ __forceinline__ uint32_t smem_u32(const void* p) {
    uint32_t a;
    asm("{ .reg .u64 t; cvta.to.shared.u64 t, %1; cvt.u32.u64 %0, t; }" : "=r"(a) : "l"(p));
    return a;
}

#define CP16(dst_u32, src_ptr) \
    asm volatile("cp.async.cg.shared.global [%0], [%1], 16;" :: "r"(dst_u32), "l"(src_ptr))
#define CP_COMMIT() asm volatile("cp.async.commit_group;" ::: "memory")
#define CP_WAIT1()  asm volatile("cp.async.wait_group 1;" ::: "memory")
#define CP_WAIT0()  asm volatile("cp.async.wait_group 0;" ::: "memory")

#define LDSM4(R, addr) \
    asm volatile("ldmatrix.sync.aligned.m8n8.x4.shared.b16 {%0,%1,%2,%3}, [%4];" \
        : "=r"((R)[0]), "=r"((R)[1]), "=r"((R)[2]), "=r"((R)[3]) : "r"(addr))

#define MMA16816(acc4, a4, b0, b1) \
    asm volatile("mma.sync.aligned.m16n8k16.row.col.f32.bf16.bf16.f32 " \
        "{%0,%1,%2,%3},{%4,%5,%6,%7},{%8,%9},{%0,%1,%2,%3};" \
        : "+f"((acc4)[0]), "+f"((acc4)[1]), "+f"((acc4)[2]), "+f"((acc4)[3]) \
        : "r"((a4)[0]), "r"((a4)[1]), "r"((a4)[2]), "r"((a4)[3]), "r"(b0), "r"(b1))

__device__ __forceinline__ uint32_t pack_bf2(float a, float b) {
    __nv_bfloat162 t = __floats2bfloat162_rn(a, b);
    return *(uint32_t*)&t;
}

// ================= prep: split A fp32 -> bf16 hi/lo =================
__global__ void k_split_a(const float* __restrict__ hs)
{
    long g = (long)blockIdx.x * 256 + threadIdx.x;   // 524288 threads, 8 floats each
    const float4* in = (const float4*)hs;
    float4 x0 = in[2 * g], x1 = in[2 * g + 1];
    float v[8] = {x0.x, x0.y, x0.z, x0.w, x1.x, x1.y, x1.z, x1.w};
    float hv[8], lv[8];
    #pragma unroll
    for (int i = 0; i < 8; i++) {
        __nv_bfloat16 h = __float2bfloat16_rn(v[i]);
        hv[i] = __bfloat162float(h);
        lv[i] = v[i] - hv[i];
    }
    uint4 ph, pl;
    ph.x = pack_bf2(hv[0], hv[1]); ph.y = pack_bf2(hv[2], hv[3]);
    ph.z = pack_bf2(hv[4], hv[5]); ph.w = pack_bf2(hv[6], hv[7]);
    pl.x = pack_bf2(lv[0], lv[1]); pl.y = pack_bf2(lv[2], lv[3]);
    pl.z = pack_bf2(lv[4], lv[5]); pl.w = pack_bf2(lv[6], lv[7]);
    ((uint4*)g_Ahb)[g] = ph;
    ((uint4*)g_Alb)[g] = pl;
}

// ================= prep: transpose + split w1 -> [n][k] bf16 hi/lo =================
__global__ void k_split_b(const float* __restrict__ w1)
{
    __shared__ float t[32][33];
    int tx = threadIdx.x, ty = threadIdx.y;
    int kb = blockIdx.y * 32, nb = blockIdx.x * 32;
    #pragma unroll
    for (int j = 0; j < 4; j++) {
        int kk = ty + j * 8;
        t[kk][tx] = w1[(long)(kb + kk) * 1024 + nb + tx];
    }
    __syncthreads();
    #pragma unroll
    for (int j = 0; j < 4; j++) {
        int nn = ty + j * 8;
        float x = t[tx][nn];
        __nv_bfloat16 h = __float2bfloat16_rn(x);
        float hf = __bfloat162float(h);
        long o = (long)(nb + nn) * 1024 + kb + tx;
        g_Bhb[o] = h;
        g_Blb[o] = __float2bfloat16_rn(x - hf);
    }
}

// ================= avg features =================
__global__ void k_avg1(const float* __restrict__ hs)
{
    int b = blockIdx.x, c = blockIdx.y, h = threadIdx.x;
    const float* p = hs + (long)b * 2048 * 1024 + (long)c * 32 * 1024 + h;
    float s = 0.f;
    #pragma unroll 4
    for (int t = 0; t < 32; t++) s += p[(long)t * 1024];
    g_avgp[(b * 64 + c) * 1024 + h] = s;
}
__global__ void k_avg2()
{
    int b = blockIdx.x, h = threadIdx.x;
    float s = 0.f;
    #pragma unroll
    for (int c = 0; c < 64; c++) s += g_avgp[(b * 64 + c) * 1024 + h];
    g_avg[b * 1024 + h] = s * (1.f / 2048.f);
}

// ================= cache MLP =================
__global__ void k_cache1(const float* __restrict__ wc1, const float* __restrict__ cache)
{
    __shared__ float comb[129];
    int b = blockIdx.x, jt = blockIdx.y, ks = blockIdx.z;
    for (int ii = threadIdx.x; ii < 129; ii += 128) {
        int i = ks * 129 + ii;
        comb[ii] = (i < 1024) ? g_avg[b * 1024 + i] : cache[i - 1024];
    }
    __syncthreads();
    int j = jt * 128 + threadIdx.x;
    const float* w = wc1 + (long)(ks * 129) * 1024 + j;
    float acc = 0.f;
    #pragma unroll 8
    for (int ii = 0; ii < 129; ii++) acc = fmaf(comb[ii], w[(long)ii * 1024], acc);
    g_c1p[(ks * 2 + b) * 1024 + j] = acc;
}
__global__ void k_cache1r(const float* __restrict__ bc1)
{
    int b = blockIdx.x, j = threadIdx.x;
    float acc = bc1[j];
    #pragma unroll
    for (int ks = 0; ks < 8; ks++) acc += g_c1p[(ks * 2 + b) * 1024 + j];
    g_hc[b * 1024 + j] = fmaxf(acc, 0.f);
}
__global__ void k_cache2(const float* __restrict__ wc2, const float* __restrict__ bc2)
{
    __shared__ float red[128];
    int b = blockIdx.x, e = blockIdx.y, tid = threadIdx.x;
    float acc = 0.f;
    #pragma unroll
    for (int j = 0; j < 8; j++) {
        int i = j * 128 + tid;
        acc = fmaf(g_hc[b * 1024 + i], wc2[i * 8 + e], acc);
    }
    red[tid] = acc;
    __syncthreads();
    for (int off = 64; off > 0; off >>= 1) {
        if (tid < off) red[tid] += red[tid + off];
        __syncthreads();
    }
    if (tid == 0) g_adj[b * 8 + e] = tanhf(red[0] + bc2[e]);
}

// ================= big kernel: bf16x3 MMA GEMM1 + fused GEMM2 partials + zero-fill =================
// grid 256 (32 M x 8 N), 256 threads (8 warps = 2m x 4n, warp tile 64x32), BK=32, 2-stage cp.async
#define OFF_BIAS 0
#define OFF_W2   512
#define OFF_STG  5120
#define A_LO_OFF 10240
#define B_OFF    20480
#define STAGE    40960
#define DYNSMEM  (OFF_STG + 2 * STAGE)

__device__ __forceinline__ void load_stage(uint32_t stg, int tid, int m0, int n0, int k0)
{
    #pragma unroll
    for (int j = 0; j < 2; j++) {
        int idx = tid + j * 256;           // 0..511
        int r = idx >> 2, c = idx & 3;
        uint32_t da = stg + r * 80 + c * 16;
        const __nv_bfloat16* sa = g_Ahb + (long)(m0 + r) * 1024 + k0 + c * 8;
        const __nv_bfloat16* sal = g_Alb + (long)(m0 + r) * 1024 + k0 + c * 8;
        CP16(da, sa);
        CP16(da + A_LO_OFF, sal);
        uint32_t db = stg + B_OFF + r * 80 + c * 16;
        const __nv_bfloat16* sb = g_Bhb + (long)(n0 + r) * 1024 + k0 + c * 8;
        const __nv_bfloat16* sbl = g_Blb + (long)(n0 + r) * 1024 + k0 + c * 8;
        CP16(db, sb);
        CP16(db + A_LO_OFF, sbl);
    }
}

__global__ __launch_bounds__(256, 1)
void k_gemm(const float* __restrict__ b1, const float* __restrict__ w2,
            float* __restrict__ out)
{
    extern __shared__ char smraw[];
    const uint32_t sb = smem_u32(smraw);

    const int tid = threadIdx.x;
    const int warp = tid >> 5;
    const int lane = tid & 31;
    const int wm = warp >> 2;          // 0..1
    const int wn = warp & 3;           // 0..3
    const int gg = lane >> 2;          // 0..7
    const int tt = lane & 3;           // 0..3
    const int blockN = blockIdx.x & 7;
    const int blockM = blockIdx.x >> 3;
    const int m0 = blockM * 128;
    const int n0 = blockN * 128;

    float* sBias = (float*)(smraw + OFF_BIAS);
    float* sW2   = (float*)(smraw + OFF_W2);
    if (tid < 128) sBias[tid] = b1[n0 + tid];
    ((float4*)sW2)[tid] = ((const float4*)(w2 + (long)n0 * 8))[tid];

    // lane-invariant ldmatrix address components
    const uint32_t aRowOff = (uint32_t)((wm * 64 + (lane & 15)) * 80) + ((lane >> 4) << 4);
    const uint32_t bRowOff = (uint32_t)((wn * 32 + (lane & 7) + ((lane & 16) >> 1)) * 80)
                             + ((lane & 8) << 1);

    float acc[4][4][4];
    #pragma unroll
    for (int f = 0; f < 4; f++)
        #pragma unroll
        for (int n = 0; n < 4; n++)
            #pragma unroll
            for (int q = 0; q < 4; q++) acc[f][n][q] = 0.f;

    load_stage(sb + OFF_STG, tid, m0, n0, 0);
    CP_COMMIT();
    load_stage(sb + OFF_STG + STAGE, tid, m0, n0, 32);
    CP_COMMIT();

    uint4* zp = (uint4*)out;
    uint4 zv; zv.x = zv.y = zv.z = zv.w = 0u;
    const long zg = (long)blockIdx.x * 256 + tid;

    for (int kt = 0; kt < 32; kt++) {
        const int cur = kt & 1;
        const uint32_t stgA = sb + OFF_STG + cur * STAGE;
        const uint32_t stgB = stgA + B_OFF;

        if (kt == 31) { CP_WAIT0(); } else { CP_WAIT1(); }
        __syncthreads();

        #pragma unroll
        for (int sub = 0; sub < 2; sub++) {
            uint32_t ah[4][4], al[4][4];
            #pragma unroll
            for (int f = 0; f < 4; f++) {
                uint32_t aa = stgA + aRowOff + f * 1280 + sub * 32;
                LDSM4(ah[f], aa);
                LDSM4(al[f], aa + A_LO_OFF);
            }
            #pragma unroll
            for (int np = 0; np < 2; np++) {
                uint32_t ba = stgB + bRowOff + np * 1280 + sub * 32;
                uint32_t bh[4], bl[4];
                LDSM4(bh, ba);
                LDSM4(bl, ba + A_LO_OFF);
                #pragma unroll
                for (int f = 0; f < 4; f++) {
                    MMA16816(acc[f][2 * np],     ah[f], bh[0], bh[1]);
                    MMA16816(acc[f][2 * np],     ah[f], bl[0], bl[1]);
                    MMA16816(acc[f][2 * np],     al[f], bh[0], bh[1]);
                    MMA16816(acc[f][2 * np + 1], ah[f], bh[2], bh[3]);
                    MMA16816(acc[f][2 * np + 1], ah[f], bl[2], bl[3]);
                    MMA16816(acc[f][2 * np + 1], al[f], bh[2], bh[3]);
                }
            }
        }

        // interleaved zero-fill of dispatch+combine (402 MB across grid)
        #pragma unroll 4
        for (int j = 0; j < 12; j++)
            zp[(long)(kt * 12 + j) * 65536 + zg] = zv;

        __syncthreads();
        if (kt < 30) {
            load_stage(stgA, tid, m0, n0, (kt + 2) * 32);
            CP_COMMIT();
        }
    }

    // epilogue: +bias, relu, partial logits = relu(h) @ w2 slice (32 cols per warp)
    const int pslice = blockN * 4 + wn;
    #pragma unroll
    for (int f = 0; f < 4; f++) {
        float le0[8] = {0,0,0,0,0,0,0,0};
        float le1[8] = {0,0,0,0,0,0,0,0};
        #pragma unroll
        for (int nf = 0; nf < 4; nf++) {
            int cb = wn * 32 + nf * 8 + tt * 2;
            float bv0 = sBias[cb], bv1 = sBias[cb + 1];
            float h00 = fmaxf(acc[f][nf][0] + bv0, 0.f);
            float h01 = fmaxf(acc[f][nf][1] + bv1, 0.f);
            float h10 = fmaxf(acc[f][nf][2] + bv0, 0.f);
            float h11 = fmaxf(acc[f][nf][3] + bv1, 0.f);
            const float* w0 = &sW2[cb * 8];
            const float* w1p = &sW2[(cb + 1) * 8];
            #pragma unroll
            for (int e = 0; e < 8; e++) {
                le0[e] += h00 * w0[e] + h01 * w1p[e];
                le1[e] += h10 * w0[e] + h11 * w1p[e];
            }
        }
        #pragma unroll
        for (int e = 0; e < 8; e++) {
            le0[e] += __shfl_xor_sync(0xffffffffu, le0[e], 1);
            le0[e] += __shfl_xor_sync(0xffffffffu, le0[e], 2);
            le1[e] += __shfl_xor_sync(0xffffffffu, le1[e], 1);
            le1[e] += __shfl_xor_sync(0xffffffffu, le1[e], 2);
        }
        if (tt == 0) {
            long row0 = m0 + wm * 64 + f * 16 + gg;
            float* p0 = g_plog + ((long)pslice * 4096 + row0) * 8;
            *(float4*)p0       = make_float4(le0[0], le0[1], le0[2], le0[3]);
            *(float4*)(p0 + 4) = make_float4(le0[4], le0[5], le0[6], le0[7]);
            float* p1 = g_plog + ((long)pslice * 4096 + row0 + 8) * 8;
            *(float4*)p1       = make_float4(le1[0], le1[1], le1[2], le1[3]);
            *(float4*)(p1 + 4) = make_float4(le1[4], le1[5], le1[6], le1[7]);
        }
    }
}

// ================= final: logits -> softmax -> top2 + per-block prob sums =================
__global__ void k_final(const float* __restrict__ b2, float* __restrict__ out)
{
    __shared__ float red[128];
    int tid = threadIdx.x;
    int tok = blockIdx.x * 128 + tid;
    int b = tok >> 11;

    float l[8] = {0,0,0,0,0,0,0,0};
    #pragma unroll 8
    for (int q = 0; q < 32; q++) {
        const float4* p = (const float4*)(g_plog + ((long)q * 4096 + tok) * 8);
        float4 u = p[0], v = p[1];
        l[0] += u.x; l[1] += u.y; l[2] += u.z; l[3] += u.w;
        l[4] += v.x; l[5] += v.y; l[6] += v.z; l[7] += v.w;
    }
    float m = -1e30f;
    #pragma unroll
    for (int e = 0; e < 8; e++) {
        l[e] += b2[e] + g_adj[b * 8 + e];
        m = fmaxf(m, l[e]);
    }
    float p[8], s = 0.f;
    #pragma unroll
    for (int e = 0; e < 8; e++) { p[e] = expf(l[e] - m); s += p[e]; }
    float inv = 1.f / s;
    #pragma unroll
    for (int e = 0; e < 8; e++) p[e] *= inv;
    {
        float* pr = out + PROBS_OFF + (long)tok * 8;
        *(float4*)pr       = make_float4(p[0], p[1], p[2], p[3]);
        *(float4*)(pr + 4) = make_float4(p[4], p[5], p[6], p[7]);
    }
    int e1 = 0;
    #pragma unroll
    for (int e = 1; e < 8; e++) if (p[e] > p[e1]) e1 = e;
    int e2 = (e1 == 0) ? 1 : 0;
    #pragma unroll
    for (int e = 0; e < 8; e++) if (e != e1 && p[e] > p[e2]) e2 = e;
    float d = p[e1] + p[e2] + 1e-8f;
    g_topk_e[tok * 2]     = e1;
    g_topk_e[tok * 2 + 1] = e2;
    g_topk_p[tok * 2]     = p[e1] / d;
    g_topk_p[tok * 2 + 1] = p[e2] / d;

    for (int e = 0; e < 8; e++) {
        red[tid] = p[e];
        __syncthreads();
        for (int off = 64; off > 0; off >>= 1) {
            if (tid < off) red[tid] += red[tid + off];
            __syncthreads();
        }
        if (tid == 0) g_psum[blockIdx.x * 8 + e] = red[0];
        __syncthreads();
    }
}

// ================= serial-order capacity scan + scatter + aux =================
__global__ void k_scan(float* __restrict__ out)
{
    __shared__ unsigned int ss[4 * 1024];
    __shared__ float psum[8];
    const int tid = threadIdx.x;

    if (tid < 8) {
        float s = 0.f;
        #pragma unroll
        for (int blk = 0; blk < 32; blk++) s += g_psum[blk * 8 + tid];
        psum[tid] = s;
    }

    int myE[8]; float myP[8];
    unsigned int c[4] = {0, 0, 0, 0};
    #pragma unroll
    for (int j = 0; j < 8; j++) {
        int n = tid * 8 + j;
        int e = g_topk_e[n];
        myE[j] = e;
        myP[j] = g_topk_p[n];
        c[e >> 1] += 1u << ((e & 1) * 16);
    }
    #pragma unroll
    for (int w = 0; w < 4; w++) ss[w * 1024 + tid] = c[w];
    __syncthreads();
    for (int off = 1; off < 1024; off <<= 1) {
        unsigned int a[4] = {0, 0, 0, 0};
        if (tid >= off) {
            #pragma unroll
            for (int w = 0; w < 4; w++) a[w] = ss[w * 1024 + tid - off];
        }
        __syncthreads();
        if (tid >= off) {
            #pragma unroll
            for (int w = 0; w < 4; w++) ss[w * 1024 + tid] += a[w];
        }
        __syncthreads();
    }
    int run[8];
    #pragma unroll
    for (int w = 0; w < 4; w++) {
        unsigned int exc = ss[w * 1024 + tid] - c[w];
        run[2 * w]     = (int)(exc & 0xffffu);
        run[2 * w + 1] = (int)(exc >> 16);
    }

    float* disp = out;
    float* comb = out + DISP_ELEMS;
    #pragma unroll
    for (int j = 0; j < 8; j++) {
        int n = tid * 8 + j;
        int e = myE[j];
        int pos = run[e]++;
        if (pos < CAP) {
            long tok = n >> 1;
            long o = tok * 12288L + (long)e * 1536L + pos;
            disp[o] = 1.0f;
            comb[o] = myP[j];
        }
    }

    if (tid == 0) {
        float aux = 0.f;
        #pragma unroll
        for (int e = 0; e < 8; e++) {
            unsigned int inc = ss[(e >> 1) * 1024 + 1023];
            float cnt = (float)((inc >> ((e & 1) * 16)) & 0xffffu);
            aux += (psum[e] * (1.f / 4096.f)) * (cnt * (1.f / 8192.f));
        }
        out[AUX_OFF] = aux * 8.f;
    }
}

// ---------------- launch ----------------
extern "C" void kernel_launch(void* const* d_in, const int* in_sizes, int n_in,
                              void* d_out, int out_size)
{
    const float* hs    = (const float*)d_in[0];
    const float* w1    = (const float*)d_in[1];
    const float* b1    = (const float*)d_in[2];
    const float* w2    = (const float*)d_in[3];
    const float* b2    = (const float*)d_in[4];
    const float* wc1   = (const float*)d_in[5];
    const float* bc1   = (const float*)d_in[6];
    const float* wc2   = (const float*)d_in[7];
    const float* bc2   = (const float*)d_in[8];
    const float* cache = (const float*)d_in[9];
    float* out = (float*)d_out;

    static int smem_set = 0;
    if (!smem_set) {
        cudaFuncSetAttribute(k_gemm, cudaFuncAttributeMaxDynamicSharedMemorySize, DYNSMEM);
        smem_set = 1;
    }

    k_split_a<<<2048, 256>>>(hs);
    k_split_b<<<dim3(32, 32), dim3(32, 8)>>>(w1);
    k_avg1<<<dim3(2, 64), 1024>>>(hs);
    k_avg2<<<2, 1024>>>();
    k_cache1<<<dim3(2, 8, 8), 128>>>(wc1, cache);
    k_cache1r<<<2, 1024>>>(bc1);
    k_cache2<<<dim3(2, 8), 128>>>(wc2, bc2);
    k_gemm<<<256, 256, DYNSMEM>>>(b1, w2, out);
    k_final<<<32, 128>>>(b2, out);
    k_scan<<<1, 1024>>>(out);
}

// round 4
// speedup vs baseline: 2.4079x; 1.2314x over previous
#include <cuda_runtime.h>
#include <cuda_bf16.h>
#include <math.h>
#include <stdint.h>

// ---------------- problem constants ----------------
// B=2, S=2048, H=1024, E=8, K=2, capacity = int(2*2048*1.5*2/8) = 1536
#define TOKENS      4096
#define HID         1024
#define NEXP        8
#define CAP         1536
#define NSLOTS      8192
#define DISP_ELEMS  50331648L
#define ZERO_ELEMS  100663296L
#define PROBS_OFF   100663296L
#define AUX_OFF     100696064L

// ---------------- device scratch ----------------
__device__ __align__(128) __nv_bfloat16 g_Ahb[TOKENS * HID];
__device__ __align__(128) __nv_bfloat16 g_Alb[TOKENS * HID];
__device__ __align__(128) __nv_bfloat16 g_Bhb[HID * HID];   // w1^T: [n][k]
__device__ __align__(128) __nv_bfloat16 g_Blb[HID * HID];
__device__ __align__(128) float g_plog[32 * TOKENS * NEXP]; // partial logits
__device__ __align__(128) float g_avgp[128 * 1024];         // per-32-token column partials
__device__ float g_adj[16];
__device__ float g_psum[32 * 8];
__device__ int   g_topk_e[NSLOTS];
__device__ float g_topk_p[NSLOTS];

// ---------------- PTX helpers (portable: sm_80+) ----------------
__device__ __forceinline__ uint32_t smem_u32(const void* p) {
    uint32_t a;
    asm("{ .reg .u64 t; cvta.to.shared.u64 t, %1; cvt.u32.u64 %0, t; }" : "=r"(a) : "l"(p));
    return a;
}

#define CP16(dst_u32, src_ptr) \
    asm volatile("cp.async.cg.shared.global [%0], [%1], 16;" :: "r"(dst_u32), "l"(src_ptr))
#define CP_COMMIT() asm volatile("cp.async.commit_group;" ::: "memory")
#define CP_WAIT1()  asm volatile("cp.async.wait_group 1;" ::: "memory")
#define CP_WAIT0()  asm volatile("cp.async.wait_group 0;" ::: "memory")

#define LDSM4(R, addr) \
    asm volatile("ldmatrix.sync.aligned.m8n8.x4.shared.b16 {%0,%1,%2,%3}, [%4];" \
        : "=r"((R)[0]), "=r"((R)[1]), "=r"((R)[2]), "=r"((R)[3]) : "r"(addr))

#define MMA16816(acc4, a4, b0, b1) \
    asm volatile("mma.sync.aligned.m16n8k16.row.col.f32.bf16.bf16.f32 " \
        "{%0,%1,%2,%3},{%4,%5,%6,%7},{%8,%9},{%0,%1,%2,%3};" \
        : "+f"((acc4)[0]), "+f"((acc4)[1]), "+f"((acc4)[2]), "+f"((acc4)[3]) \
        : "r"((a4)[0]), "r"((a4)[1]), "r"((a4)[2]), "r"((a4)[3]), "r"(b0), "r"(b1))

__device__ __forceinline__ uint32_t pack_bf2(float a, float b) {
    __nv_bfloat162 t = __floats2bfloat162_rn(a, b);
    return *(uint32_t*)&t;
}

// ============ k_prep: split A fp32 -> bf16 hi/lo  +  avg column partials ============
// grid 128 (32 tokens each), 256 threads (one float4 column each)
__global__ void k_prep(const float* __restrict__ hs)
{
    const int blk = blockIdx.x;
    const int tid = threadIdx.x;
    const float4* in = (const float4*)(hs + (long)blk * 32 * 1024) + tid;
    uint2* ah = ((uint2*)g_Ahb) + (long)blk * 32 * 256 + tid;
    uint2* al = ((uint2*)g_Alb) + (long)blk * 32 * 256 + tid;
    float4 s = make_float4(0.f, 0.f, 0.f, 0.f);
    #pragma unroll 4
    for (int t = 0; t < 32; t++) {
        float4 x = in[(long)t * 256];
        s.x += x.x; s.y += x.y; s.z += x.z; s.w += x.w;
        float h0 = __bfloat162float(__float2bfloat16_rn(x.x));
        float h1 = __bfloat162float(__float2bfloat16_rn(x.y));
        float h2 = __bfloat162float(__float2bfloat16_rn(x.z));
        float h3 = __bfloat162float(__float2bfloat16_rn(x.w));
        uint2 ph, pl;
        ph.x = pack_bf2(h0, h1);           ph.y = pack_bf2(h2, h3);
        pl.x = pack_bf2(x.x - h0, x.y - h1); pl.y = pack_bf2(x.z - h2, x.w - h3);
        ah[(long)t * 256] = ph;
        al[(long)t * 256] = pl;
    }
    ((float4*)(g_avgp + (long)blk * 1024))[tid] = s;
}

// ============ k_split_b: transpose + split w1 -> [n][k] bf16 hi/lo ============
__global__ void k_split_b(const float* __restrict__ w1)
{
    __shared__ float t[32][33];
    int tx = threadIdx.x, ty = threadIdx.y;
    int kb = blockIdx.y * 32, nb = blockIdx.x * 32;
    #pragma unroll
    for (int j = 0; j < 4; j++) {
        int kk = ty + j * 8;
        t[kk][tx] = w1[(long)(kb + kk) * 1024 + nb + tx];
    }
    __syncthreads();
    #pragma unroll
    for (int j = 0; j < 4; j++) {
        int nn = ty + j * 8;
        float x = t[tx][nn];
        __nv_bfloat16 h = __float2bfloat16_rn(x);
        float hf = __bfloat162float(h);
        long o = (long)(nb + nn) * 1024 + kb + tx;
        g_Bhb[o] = h;
        g_Blb[o] = __float2bfloat16_rn(x - hf);
    }
}

// ============ big kernel: bf16x3 MMA GEMM1 + fused GEMM2 partials + zero-fill
//              + 2 side CTAs running the whole cache-MLP path concurrently ============
// gemm part: grid blocks 0..255 (32 M x 8 N), 256 threads (2m x 4n warps, warp tile 64x32),
// BK=32, 3-slot prefetch-2 cp.async pipeline.
#define OFF_BIAS 0
#define OFF_W2   512
#define OFF_STG  5120
#define A_LO_OFF 10240
#define B_OFF    20480
#define STAGE    40960
#define DYNSMEM  (OFF_STG + 3 * STAGE)

__device__ __forceinline__ void load_stage(uint32_t stg, int tid, int m0, int n0, int k0)
{
    #pragma unroll
    for (int j = 0; j < 2; j++) {
        int idx = tid + j * 256;           // 0..511
        int r = idx >> 2, c = idx & 3;
        uint32_t da = stg + r * 80 + c * 16;
        CP16(da,            g_Ahb + (long)(m0 + r) * 1024 + k0 + c * 8);
        CP16(da + A_LO_OFF, g_Alb + (long)(m0 + r) * 1024 + k0 + c * 8);
        uint32_t db = stg + B_OFF + r * 80 + c * 16;
        CP16(db,            g_Bhb + (long)(n0 + r) * 1024 + k0 + c * 8);
        CP16(db + A_LO_OFF, g_Blb + (long)(n0 + r) * 1024 + k0 + c * 8);
    }
}

__global__ __launch_bounds__(256, 1)
void k_gemm(const float* __restrict__ b1, const float* __restrict__ w2,
            const float* __restrict__ wc1, const float* __restrict__ bc1,
            const float* __restrict__ wc2, const float* __restrict__ bc2,
            const float* __restrict__ cache, float* __restrict__ out)
{
    extern __shared__ char smraw[];
    const uint32_t sb = smem_u32(smraw);
    const int tid = threadIdx.x;
    const int warp = tid >> 5;
    const int lane = tid & 31;

    // ---------- side CTAs: cache-MLP path (runs concurrently with GEMM) ----------
    if (blockIdx.x >= 256) {
        const int b = blockIdx.x - 256;
        float* comb = (float*)smraw;             // 1032 floats
        float* hcS  = (float*)(smraw + 4224);    // 1024 floats
        // avg finalize
        {
            float4 s = make_float4(0.f, 0.f, 0.f, 0.f);
            const float4* ap = (const float4*)(g_avgp + (long)b * 64 * 1024) + tid;
            #pragma unroll 8
            for (int c = 0; c < 64; c++) {
                float4 v = ap[(long)c * 256];
                s.x += v.x; s.y += v.y; s.z += v.z; s.w += v.w;
            }
            const float inv = 1.f / 2048.f;
            ((float4*)comb)[tid] = make_float4(s.x * inv, s.y * inv, s.z * inv, s.w * inv);
            if (tid < 8) comb[1024 + tid] = cache[tid];
        }
        __syncthreads();
        // c1: hc = relu(comb @ wc1 + bc1), each thread 4 output cols
        {
            int j = tid * 4;
            float4 acc = *(const float4*)(bc1 + j);
            const float4* wp = (const float4*)(wc1 + j);
            for (int i = 0; i < 1032; i++) {
                float cv = comb[i];
                float4 w = wp[(long)i * 256];
                acc.x = fmaf(cv, w.x, acc.x);
                acc.y = fmaf(cv, w.y, acc.y);
                acc.z = fmaf(cv, w.z, acc.z);
                acc.w = fmaf(cv, w.w, acc.w);
            }
            hcS[j]     = fmaxf(acc.x, 0.f);
            hcS[j + 1] = fmaxf(acc.y, 0.f);
            hcS[j + 2] = fmaxf(acc.z, 0.f);
            hcS[j + 3] = fmaxf(acc.w, 0.f);
        }
        __syncthreads();
        // c2: adj = tanh(hc @ wc2 + bc2), one warp per expert
        {
            float acc = 0.f;
            for (int i = lane; i < 1024; i += 32)
                acc = fmaf(hcS[i], wc2[i * 8 + warp], acc);
            #pragma unroll
            for (int off = 16; off > 0; off >>= 1)
                acc += __shfl_down_sync(0xffffffffu, acc, off);
            if (lane == 0) g_adj[b * 8 + warp] = tanhf(acc + bc2[warp]);
        }
        return;
    }

    // ---------- GEMM CTAs ----------
    const int wm = warp >> 2;          // 0..1
    const int wn = warp & 3;           // 0..3
    const int gg = lane >> 2;          // 0..7
    const int tt = lane & 3;           // 0..3
    const int blockN = blockIdx.x & 7;
    const int blockM = blockIdx.x >> 3;
    const int m0 = blockM * 128;
    const int n0 = blockN * 128;

    float* sBias = (float*)(smraw + OFF_BIAS);
    float* sW2   = (float*)(smraw + OFF_W2);
    if (tid < 128) sBias[tid] = b1[n0 + tid];
    ((float4*)sW2)[tid] = ((const float4*)(w2 + (long)n0 * 8))[tid];

    const uint32_t aRowOff = (uint32_t)((wm * 64 + (lane & 15)) * 80) + ((lane >> 4) << 4);
    const uint32_t bRowOff = (uint32_t)((wn * 32 + (lane & 7) + ((lane & 16) >> 1)) * 80)
                             + ((lane & 8) << 1);

    float acc[4][4][4];
    #pragma unroll
    for (int f = 0; f < 4; f++)
        #pragma unroll
        for (int n = 0; n < 4; n++)
            #pragma unroll
            for (int q = 0; q < 4; q++) acc[f][n][q] = 0.f;

    // prologue: prefetch stages for kt=0,1 into slots 0,1
    load_stage(sb + OFF_STG,          tid, m0, n0, 0);
    CP_COMMIT();
    load_stage(sb + OFF_STG + STAGE,  tid, m0, n0, 32);
    CP_COMMIT();

    uint4* zp = (uint4*)out;
    uint4 zv; zv.x = zv.y = zv.z = zv.w = 0u;
    const long zg = (long)blockIdx.x * 256 + tid;

    for (int kt = 0; kt < 32; kt++) {
        const int slot = kt % 3;
        const uint32_t stgA = sb + OFF_STG + slot * STAGE;
        const uint32_t stgB = stgA + B_OFF;

        if (kt < 31) { CP_WAIT1(); } else { CP_WAIT0(); }
        __syncthreads();

        // prefetch kt+2 into slot (kt+2)%3 (free: all warps finished kt-1)
        if (kt < 30) {
            load_stage(sb + OFF_STG + ((kt + 2) % 3) * STAGE, tid, m0, n0, (kt + 2) * 32);
            CP_COMMIT();
        }

        #pragma unroll
        for (int sub = 0; sub < 2; sub++) {
            uint32_t ah[4][4], al[4][4];
            #pragma unroll
            for (int f = 0; f < 4; f++) {
                uint32_t aa = stgA + aRowOff + f * 1280 + sub * 32;
                LDSM4(ah[f], aa);
                LDSM4(al[f], aa + A_LO_OFF);
            }
            #pragma unroll
            for (int np = 0; np < 2; np++) {
                uint32_t ba = stgB + bRowOff + np * 1280 + sub * 32;
                uint32_t bh[4], bl[4];
                LDSM4(bh, ba);
                LDSM4(bl, ba + A_LO_OFF);
                #pragma unroll
                for (int f = 0; f < 4; f++) {
                    MMA16816(acc[f][2 * np],     ah[f], bh[0], bh[1]);
                    MMA16816(acc[f][2 * np],     ah[f], bl[0], bl[1]);
                    MMA16816(acc[f][2 * np],     al[f], bh[0], bh[1]);
                    MMA16816(acc[f][2 * np + 1], ah[f], bh[2], bh[3]);
                    MMA16816(acc[f][2 * np + 1], ah[f], bl[2], bl[3]);
                    MMA16816(acc[f][2 * np + 1], al[f], bh[2], bh[3]);
                }
            }
        }

        // interleaved zero-fill of dispatch+combine (402 MB across 256 CTAs)
        #pragma unroll 4
        for (int j = 0; j < 12; j++)
            zp[(long)(kt * 12 + j) * 65536 + zg] = zv;
    }

    // epilogue: +bias, relu, partial logits = relu(h) @ w2 slice
    const int pslice = blockN * 4 + wn;
    #pragma unroll
    for (int f = 0; f < 4; f++) {
        float le0[8] = {0,0,0,0,0,0,0,0};
        float le1[8] = {0,0,0,0,0,0,0,0};
        #pragma unroll
        for (int nf = 0; nf < 4; nf++) {
            int cb = wn * 32 + nf * 8 + tt * 2;
            float bv0 = sBias[cb], bv1 = sBias[cb + 1];
            float h00 = fmaxf(acc[f][nf][0] + bv0, 0.f);
            float h01 = fmaxf(acc[f][nf][1] + bv1, 0.f);
            float h10 = fmaxf(acc[f][nf][2] + bv0, 0.f);
            float h11 = fmaxf(acc[f][nf][3] + bv1, 0.f);
            const float* w0 = &sW2[cb * 8];
            const float* w1p = &sW2[(cb + 1) * 8];
            #pragma unroll
            for (int e = 0; e < 8; e++) {
                le0[e] += h00 * w0[e] + h01 * w1p[e];
                le1[e] += h10 * w0[e] + h11 * w1p[e];
            }
        }
        #pragma unroll
        for (int e = 0; e < 8; e++) {
            le0[e] += __shfl_xor_sync(0xffffffffu, le0[e], 1);
            le0[e] += __shfl_xor_sync(0xffffffffu, le0[e], 2);
            le1[e] += __shfl_xor_sync(0xffffffffu, le1[e], 1);
            le1[e] += __shfl_xor_sync(0xffffffffu, le1[e], 2);
        }
        if (tt == 0) {
            long row0 = m0 + wm * 64 + f * 16 + gg;
            float* p0 = g_plog + ((long)pslice * 4096 + row0) * 8;
            *(float4*)p0       = make_float4(le0[0], le0[1], le0[2], le0[3]);
            *(float4*)(p0 + 4) = make_float4(le0[4], le0[5], le0[6], le0[7]);
            float* p1 = g_plog + ((long)pslice * 4096 + row0 + 8) * 8;
            *(float4*)p1       = make_float4(le1[0], le1[1], le1[2], le1[3]);
            *(float4*)(p1 + 4) = make_float4(le1[4], le1[5], le1[6], le1[7]);
        }
    }
}

// ============ k_final: logits -> softmax -> top2 + per-block prob sums ============
__global__ void k_final(const float* __restrict__ b2, float* __restrict__ out)
{
    __shared__ float red[128];
    int tid = threadIdx.x;
    int tok = blockIdx.x * 128 + tid;
    int b = tok >> 11;

    float l[8] = {0,0,0,0,0,0,0,0};
    #pragma unroll 8
    for (int q = 0; q < 32; q++) {
        const float4* p = (const float4*)(g_plog + ((long)q * 4096 + tok) * 8);
        float4 u = p[0], v = p[1];
        l[0] += u.x; l[1] += u.y; l[2] += u.z; l[3] += u.w;
        l[4] += v.x; l[5] += v.y; l[6] += v.z; l[7] += v.w;
    }
    float m = -1e30f;
    #pragma unroll
    for (int e = 0; e < 8; e++) {
        l[e] += b2[e] + g_adj[b * 8 + e];
        m = fmaxf(m, l[e]);
    }
    float p[8], s = 0.f;
    #pragma unroll
    for (int e = 0; e < 8; e++) { p[e] = expf(l[e] - m); s += p[e]; }
    float inv = 1.f / s;
    #pragma unroll
    for (int e = 0; e < 8; e++) p[e] *= inv;
    {
        float* pr = out + PROBS_OFF + (long)tok * 8;
        *(float4*)pr       = make_float4(p[0], p[1], p[2], p[3]);
        *(float4*)(pr + 4) = make_float4(p[4], p[5], p[6], p[7]);
    }
    int e1 = 0;
    #pragma unroll
    for (int e = 1; e < 8; e++) if (p[e] > p[e1]) e1 = e;
    int e2 = (e1 == 0) ? 1 : 0;
    #pragma unroll
    for (int e = 0; e < 8; e++) if (e != e1 && p[e] > p[e2]) e2 = e;
    float d = p[e1] + p[e2] + 1e-8f;
    g_topk_e[tok * 2]     = e1;
    g_topk_e[tok * 2 + 1] = e2;
    g_topk_p[tok * 2]     = p[e1] / d;
    g_topk_p[tok * 2 + 1] = p[e2] / d;

    for (int e = 0; e < 8; e++) {
        red[tid] = p[e];
        __syncthreads();
        for (int off = 64; off > 0; off >>= 1) {
            if (tid < off) red[tid] += red[tid + off];
            __syncthreads();
        }
        if (tid == 0) g_psum[blockIdx.x * 8 + e] = red[0];
        __syncthreads();
    }
}

// ============ k_scan: serial-order capacity scan + scatter + aux ============
__global__ void k_scan(float* __restrict__ out)
{
    __shared__ unsigned int ss[4 * 1024];
    __shared__ float psum[8];
    const int tid = threadIdx.x;

    if (tid < 8) {
        float s = 0.f;
        #pragma unroll
        for (int blk = 0; blk < 32; blk++) s += g_psum[blk * 8 + tid];
        psum[tid] = s;
    }

    int myE[8]; float myP[8];
    unsigned int c[4] = {0, 0, 0, 0};
    #pragma unroll
    for (int j = 0; j < 8; j++) {
        int n = tid * 8 + j;
        int e = g_topk_e[n];
        myE[j] = e;
        myP[j] = g_topk_p[n];
        c[e >> 1] += 1u << ((e & 1) * 16);
    }
    #pragma unroll
    for (int w = 0; w < 4; w++) ss[w * 1024 + tid] = c[w];
    __syncthreads();
    for (int off = 1; off < 1024; off <<= 1) {
        unsigned int a[4] = {0, 0, 0, 0};
        if (tid >= off) {
            #pragma unroll
            for (int w = 0; w < 4; w++) a[w] = ss[w * 1024 + tid - off];
        }
        __syncthreads();
        if (tid >= off) {
            #pragma unroll
            for (int w = 0; w < 4; w++) ss[w * 1024 + tid] += a[w];
        }
        __syncthreads();
    }
    int run[8];
    #pragma unroll
    for (int w = 0; w < 4; w++) {
        unsigned int exc = ss[w * 1024 + tid] - c[w];
        run[2 * w]     = (int)(exc & 0xffffu);
        run[2 * w + 1] = (int)(exc >> 16);
    }

    float* disp = out;
    float* comb = out + DISP_ELEMS;
    #pragma unroll
    for (int j = 0; j < 8; j++) {
        int n = tid * 8 + j;
        int e = myE[j];
        int pos = run[e]++;
        if (pos < CAP) {
            long tok = n >> 1;
            long o = tok * 12288L + (long)e * 1536L + pos;
            disp[o] = 1.0f;
            comb[o] = myP[j];
        }
    }

    if (tid == 0) {
        float aux = 0.f;
        #pragma unroll
        for (int e = 0; e < 8; e++) {
            unsigned int inc = ss[(e >> 1) * 1024 + 1023];
            float cnt = (float)((inc >> ((e & 1) * 16)) & 0xffffu);
            aux += (psum[e] * (1.f / 4096.f)) * (cnt * (1.f / 8192.f));
        }
        out[AUX_OFF] = aux * 8.f;
    }
}

// ---------------- launch ----------------
extern "C" void kernel_launch(void* const* d_in, const int* in_sizes, int n_in,
                              void* d_out, int out_size)
{
    const float* hs    = (const float*)d_in[0];
    const float* w1    = (const float*)d_in[1];
    const float* b1    = (const float*)d_in[2];
    const float* w2    = (const float*)d_in[3];
    const float* b2    = (const float*)d_in[4];
    const float* wc1   = (const float*)d_in[5];
    const float* bc1   = (const float*)d_in[6];
    const float* wc2   = (const float*)d_in[7];
    const float* bc2   = (const float*)d_in[8];
    const float* cache = (const float*)d_in[9];
    float* out = (float*)d_out;

    cudaFuncSetAttribute(k_gemm, cudaFuncAttributeMaxDynamicSharedMemorySize, DYNSMEM);

    k_prep<<<128, 256>>>(hs);
    k_split_b<<<dim3(32, 32), dim3(32, 8)>>>(w1);
    k_gemm<<<258, 256, DYNSMEM>>>(b1, w2, wc1, bc1, wc2, bc2, cache, out);
    k_final<<<32, 128>>>(b2, out);
    k_scan<<<1, 1024>>>(out);
}

// round 5
// speedup vs baseline: 2.5872x; 1.0745x over previous
#include <cuda_runtime.h>
#include <cuda_bf16.h>
#include <math.h>
#include <stdint.h>

// ---------------- problem constants ----------------
#define TOKENS      4096
#define HID         1024
#define NEXP        8
#define CAP         1536
#define NSLOTS      8192
#define DISP_ELEMS  50331648L
#define ZERO_ELEMS  100663296L
#define PROBS_OFF   100663296L
#define AUX_OFF     100696064L

// ---------------- device scratch ----------------
__device__ __align__(128) __nv_bfloat16 g_Ahb[TOKENS * HID];
__device__ __align__(128) __nv_bfloat16 g_Alb[TOKENS * HID];
__device__ __align__(128) __nv_bfloat16 g_Bhb[HID * HID];   // w1^T: [n][k]
__device__ __align__(128) __nv_bfloat16 g_Blb[HID * HID];
__device__ __align__(128) float g_plog[8 * TOKENS * NEXP];  // partial logits (8 N-slices)
__device__ __align__(128) float g_avgp[128 * 1024];
__device__ float g_adj[16];
__device__ float g_psum[32 * 8];
__device__ int   g_topk_e[NSLOTS];
__device__ float g_topk_p[NSLOTS];

// ---------------- PTX helpers (portable: sm_80+) ----------------
__device__ __forceinline__ uint32_t smem_u32(const void* p) {
    uint32_t a;
    asm("{ .reg .u64 t; cvta.to.shared.u64 t, %1; cvt.u32.u64 %0, t; }" : "=r"(a) : "l"(p));
    return a;
}

#define CP16(dst_u32, src_ptr) \
    asm volatile("cp.async.cg.shared.global [%0], [%1], 16;" :: "r"(dst_u32), "l"(src_ptr))
#define CP_COMMIT() asm volatile("cp.async.commit_group;" ::: "memory")
#define CP_WAIT1()  asm volatile("cp.async.wait_group 1;" ::: "memory")
#define CP_WAIT0()  asm volatile("cp.async.wait_group 0;" ::: "memory")

#define LDSM4(R, addr) \
    asm volatile("ldmatrix.sync.aligned.m8n8.x4.shared.b16 {%0,%1,%2,%3}, [%4];" \
        : "=r"((R)[0]), "=r"((R)[1]), "=r"((R)[2]), "=r"((R)[3]) : "r"(addr))

#define MMA16816(acc4, a4, b0, b1) \
    asm volatile("mma.sync.aligned.m16n8k16.row.col.f32.bf16.bf16.f32 " \
        "{%0,%1,%2,%3},{%4,%5,%6,%7},{%8,%9},{%0,%1,%2,%3};" \
        : "+f"((acc4)[0]), "+f"((acc4)[1]), "+f"((acc4)[2]), "+f"((acc4)[3]) \
        : "r"((a4)[0]), "r"((a4)[1]), "r"((a4)[2]), "r"((a4)[3]), "r"(b0), "r"(b1))

__device__ __forceinline__ uint32_t pack_bf2(float a, float b) {
    __nv_bfloat162 t = __floats2bfloat162_rn(a, b);
    return *(uint32_t*)&t;
}

// ============ k_prep: split A fp32 -> bf16 hi/lo + avg column partials ============
__global__ void k_prep(const float* __restrict__ hs)
{
    const int blk = blockIdx.x;
    const int tid = threadIdx.x;
    const float4* in = (const float4*)(hs + (long)blk * 32 * 1024) + tid;
    uint2* ah = ((uint2*)g_Ahb) + (long)blk * 32 * 256 + tid;
    uint2* al = ((uint2*)g_Alb) + (long)blk * 32 * 256 + tid;
    float4 s = make_float4(0.f, 0.f, 0.f, 0.f);
    #pragma unroll 4
    for (int t = 0; t < 32; t++) {
        float4 x = in[(long)t * 256];
        s.x += x.x; s.y += x.y; s.z += x.z; s.w += x.w;
        float h0 = __bfloat162float(__float2bfloat16_rn(x.x));
        float h1 = __bfloat162float(__float2bfloat16_rn(x.y));
        float h2 = __bfloat162float(__float2bfloat16_rn(x.z));
        float h3 = __bfloat162float(__float2bfloat16_rn(x.w));
        uint2 ph, pl;
        ph.x = pack_bf2(h0, h1);             ph.y = pack_bf2(h2, h3);
        pl.x = pack_bf2(x.x - h0, x.y - h1); pl.y = pack_bf2(x.z - h2, x.w - h3);
        ah[(long)t * 256] = ph;
        al[(long)t * 256] = pl;
    }
    ((float4*)(g_avgp + (long)blk * 1024))[tid] = s;
}

// ============ k_split_b: transpose + split w1 -> [n][k] bf16 hi/lo ============
__global__ void k_split_b(const float* __restrict__ w1)
{
    __shared__ float t[32][33];
    int tx = threadIdx.x, ty = threadIdx.y;
    int kb = blockIdx.y * 32, nb = blockIdx.x * 32;
    #pragma unroll
    for (int j = 0; j < 4; j++) {
        int kk = ty + j * 8;
        t[kk][tx] = w1[(long)(kb + kk) * 1024 + nb + tx];
    }
    __syncthreads();
    #pragma unroll
    for (int j = 0; j < 4; j++) {
        int nn = ty + j * 8;
        float x = t[tx][nn];
        __nv_bfloat16 h = __float2bfloat16_rn(x);
        float hf = __bfloat162float(h);
        long o = (long)(nb + nn) * 1024 + kb + tx;
        g_Bhb[o] = h;
        g_Blb[o] = __float2bfloat16_rn(x - hf);
    }
}

// ============ big kernel ============
#define OFF_BIAS 0
#define OFF_W2   512
#define OFF_STG  5120
#define A_LO_OFF 10240
#define B_OFF    20480
#define STAGE    40960
#define DYNSMEM  (OFF_STG + 3 * STAGE)

__device__ __forceinline__ void load_stage(uint32_t stg, int tid, int m0, int n0, int k0)
{
    #pragma unroll
    for (int j = 0; j < 2; j++) {
        int idx = tid + j * 256;
        int r = idx >> 2, c = idx & 3;
        uint32_t da = stg + r * 80 + c * 16;
        CP16(da,            g_Ahb + (long)(m0 + r) * 1024 + k0 + c * 8);
        CP16(da + A_LO_OFF, g_Alb + (long)(m0 + r) * 1024 + k0 + c * 8);
        uint32_t db = stg + B_OFF + r * 80 + c * 16;
        CP16(db,            g_Bhb + (long)(n0 + r) * 1024 + k0 + c * 8);
        CP16(db + A_LO_OFF, g_Blb + (long)(n0 + r) * 1024 + k0 + c * 8);
    }
}

__global__ __launch_bounds__(256, 1)
void k_gemm(const float* __restrict__ b1, const float* __restrict__ w2,
            const float* __restrict__ wc1, const float* __restrict__ bc1,
            const float* __restrict__ wc2, const float* __restrict__ bc2,
            const float* __restrict__ cache, float* __restrict__ out)
{
    extern __shared__ char smraw[];
    const uint32_t sb = smem_u32(smraw);
    const int tid = threadIdx.x;
    const int warp = tid >> 5;
    const int lane = tid & 31;

    // ---------- side CTAs: cache-MLP path ----------
    if (blockIdx.x >= 256) {
        const int b = blockIdx.x - 256;
        float* comb = (float*)smraw;
        float* hcS  = (float*)(smraw + 4224);
        {
            float4 s = make_float4(0.f, 0.f, 0.f, 0.f);
            const float4* ap = (const float4*)(g_avgp + (long)b * 64 * 1024) + tid;
            #pragma unroll 8
            for (int c = 0; c < 64; c++) {
                float4 v = ap[(long)c * 256];
                s.x += v.x; s.y += v.y; s.z += v.z; s.w += v.w;
            }
            const float inv = 1.f / 2048.f;
            ((float4*)comb)[tid] = make_float4(s.x * inv, s.y * inv, s.z * inv, s.w * inv);
            if (tid < 8) comb[1024 + tid] = cache[tid];
        }
        __syncthreads();
        {
            int j = tid * 4;
            float4 acc = *(const float4*)(bc1 + j);
            const float4* wp = (const float4*)(wc1 + j);
            for (int i = 0; i < 1032; i++) {
                float cv = comb[i];
                float4 w = wp[(long)i * 256];
                acc.x = fmaf(cv, w.x, acc.x);
                acc.y = fmaf(cv, w.y, acc.y);
                acc.z = fmaf(cv, w.z, acc.z);
                acc.w = fmaf(cv, w.w, acc.w);
            }
            hcS[j]     = fmaxf(acc.x, 0.f);
            hcS[j + 1] = fmaxf(acc.y, 0.f);
            hcS[j + 2] = fmaxf(acc.z, 0.f);
            hcS[j + 3] = fmaxf(acc.w, 0.f);
        }
        __syncthreads();
        {
            float acc = 0.f;
            for (int i = lane; i < 1024; i += 32)
                acc = fmaf(hcS[i], wc2[i * 8 + warp], acc);
            #pragma unroll
            for (int off = 16; off > 0; off >>= 1)
                acc += __shfl_down_sync(0xffffffffu, acc, off);
            if (lane == 0) g_adj[b * 8 + warp] = tanhf(acc + bc2[warp]);
        }
        return;
    }

    // ---------- GEMM CTAs ----------
    const int wm = warp >> 2;
    const int wn = warp & 3;
    const int gg = lane >> 2;
    const int tt = lane & 3;
    const int blockN = blockIdx.x & 7;
    const int blockM = blockIdx.x >> 3;
    const int m0 = blockM * 128;
    const int n0 = blockN * 128;

    float* sBias = (float*)(smraw + OFF_BIAS);
    float* sW2   = (float*)(smraw + OFF_W2);
    if (tid < 128) sBias[tid] = b1[n0 + tid];
    ((float4*)sW2)[tid] = ((const float4*)(w2 + (long)n0 * 8))[tid];

    const uint32_t aRowOff = (uint32_t)((wm * 64 + (lane & 15)) * 80) + ((lane >> 4) << 4);
    const uint32_t bRowOff = (uint32_t)((wn * 32 + (lane & 7) + ((lane & 16) >> 1)) * 80)
                             + ((lane & 8) << 1);

    float acc[4][4][4];
    #pragma unroll
    for (int f = 0; f < 4; f++)
        #pragma unroll
        for (int n = 0; n < 4; n++)
            #pragma unroll
            for (int q = 0; q < 4; q++) acc[f][n][q] = 0.f;

    load_stage(sb + OFF_STG,         tid, m0, n0, 0);
    CP_COMMIT();
    load_stage(sb + OFF_STG + STAGE, tid, m0, n0, 32);
    CP_COMMIT();

    uint4* zp = (uint4*)out;
    uint4 zv; zv.x = zv.y = zv.z = zv.w = 0u;
    const long zg = (long)blockIdx.x * 256 + tid;

    for (int kt = 0; kt < 32; kt++) {
        const int slot = kt % 3;
        const uint32_t stgA = sb + OFF_STG + slot * STAGE;
        const uint32_t stgB = stgA + B_OFF;

        if (kt < 31) { CP_WAIT1(); } else { CP_WAIT0(); }
        __syncthreads();

        if (kt < 30) {
            load_stage(sb + OFF_STG + ((kt + 2) % 3) * STAGE, tid, m0, n0, (kt + 2) * 32);
            CP_COMMIT();
        }

        #pragma unroll
        for (int sub = 0; sub < 2; sub++) {
            uint32_t ah[4][4], al[4][4];
            #pragma unroll
            for (int f = 0; f < 4; f++) {
                uint32_t aa = stgA + aRowOff + f * 1280 + sub * 32;
                LDSM4(ah[f], aa);
                LDSM4(al[f], aa + A_LO_OFF);
            }
            #pragma unroll
            for (int np = 0; np < 2; np++) {
                uint32_t ba = stgB + bRowOff + np * 1280 + sub * 32;
                uint32_t bh[4], bl[4];
                LDSM4(bh, ba);
                LDSM4(bl, ba + A_LO_OFF);
                #pragma unroll
                for (int f = 0; f < 4; f++) {
                    MMA16816(acc[f][2 * np],     ah[f], bh[0], bh[1]);
                    MMA16816(acc[f][2 * np],     ah[f], bl[0], bl[1]);
                    MMA16816(acc[f][2 * np],     al[f], bh[0], bh[1]);
                    MMA16816(acc[f][2 * np + 1], ah[f], bh[2], bh[3]);
                    MMA16816(acc[f][2 * np + 1], ah[f], bl[2], bl[3]);
                    MMA16816(acc[f][2 * np + 1], al[f], bh[2], bh[3]);
                }
            }
        }

        // interleaved zero-fill with L2-streaming hint (evict-first: keep L2 for A/B)
        #pragma unroll 4
        for (int j = 0; j < 12; j++)
            __stcs(zp + (long)(kt * 12 + j) * 65536 + zg, zv);
    }

    // ---------- epilogue: +bias, relu, GEMM2 partials; reduce 4 wn-warps in smem ----------
    float* sPart = (float*)(smraw + OFF_STG);   // [4][128][8] floats = 16 KB
    #pragma unroll
    for (int f = 0; f < 4; f++) {
        float le0[8] = {0,0,0,0,0,0,0,0};
        float le1[8] = {0,0,0,0,0,0,0,0};
        #pragma unroll
        for (int nf = 0; nf < 4; nf++) {
            int cb = wn * 32 + nf * 8 + tt * 2;
            float bv0 = sBias[cb], bv1 = sBias[cb + 1];
            float h00 = fmaxf(acc[f][nf][0] + bv0, 0.f);
            float h01 = fmaxf(acc[f][nf][1] + bv1, 0.f);
            float h10 = fmaxf(acc[f][nf][2] + bv0, 0.f);
            float h11 = fmaxf(acc[f][nf][3] + bv1, 0.f);
            const float* w0 = &sW2[cb * 8];
            const float* w1p = &sW2[(cb + 1) * 8];
            #pragma unroll
            for (int e = 0; e < 8; e++) {
                le0[e] += h00 * w0[e] + h01 * w1p[e];
                le1[e] += h10 * w0[e] + h11 * w1p[e];
            }
        }
        #pragma unroll
        for (int e = 0; e < 8; e++) {
            le0[e] += __shfl_xor_sync(0xffffffffu, le0[e], 1);
            le0[e] += __shfl_xor_sync(0xffffffffu, le0[e], 2);
            le1[e] += __shfl_xor_sync(0xffffffffu, le1[e], 1);
            le1[e] += __shfl_xor_sync(0xffffffffu, le1[e], 2);
        }
        if (tt == 0) {
            int r0 = wm * 64 + f * 16 + gg;
            float* p0 = &sPart[(wn * 128 + r0) * 8];
            *(float4*)p0       = make_float4(le0[0], le0[1], le0[2], le0[3]);
            *(float4*)(p0 + 4) = make_float4(le0[4], le0[5], le0[6], le0[7]);
            float* p1 = &sPart[(wn * 128 + r0 + 8) * 8];
            *(float4*)p1       = make_float4(le1[0], le1[1], le1[2], le1[3]);
            *(float4*)(p1 + 4) = make_float4(le1[4], le1[5], le1[6], le1[7]);
        }
    }
    __syncthreads();
    {
        // deterministic fixed-order reduction across the 4 wn slices
        int row = tid >> 1, e4 = (tid & 1) * 4;
        float4 v0 = *(float4*)&sPart[(0 * 128 + row) * 8 + e4];
        float4 v1 = *(float4*)&sPart[(1 * 128 + row) * 8 + e4];
        float4 v2 = *(float4*)&sPart[(2 * 128 + row) * 8 + e4];
        float4 v3 = *(float4*)&sPart[(3 * 128 + row) * 8 + e4];
        float4 v = make_float4(((v0.x + v1.x) + v2.x) + v3.x,
                               ((v0.y + v1.y) + v2.y) + v3.y,
                               ((v0.z + v1.z) + v2.z) + v3.z,
                               ((v0.w + v1.w) + v2.w) + v3.w);
        *(float4*)(g_plog + ((long)blockN * 4096 + m0 + row) * 8 + e4) = v;
    }
}

// ============ k_final: logits -> softmax -> top2 + per-block prob sums ============
__global__ void k_final(const float* __restrict__ b2, float* __restrict__ out)
{
    __shared__ float wsum[4][8];
    int tid = threadIdx.x;
    int lane = tid & 31, warp = tid >> 5;
    int tok = blockIdx.x * 128 + tid;
    int b = tok >> 11;

    float l[8] = {0,0,0,0,0,0,0,0};
    #pragma unroll
    for (int q = 0; q < 8; q++) {
        const float4* p = (const float4*)(g_plog + ((long)q * 4096 + tok) * 8);
        float4 u = p[0], v = p[1];
        l[0] += u.x; l[1] += u.y; l[2] += u.z; l[3] += u.w;
        l[4] += v.x; l[5] += v.y; l[6] += v.z; l[7] += v.w;
    }
    float m = -1e30f;
    #pragma unroll
    for (int e = 0; e < 8; e++) {
        l[e] += b2[e] + g_adj[b * 8 + e];
        m = fmaxf(m, l[e]);
    }
    float p[8], s = 0.f;
    #pragma unroll
    for (int e = 0; e < 8; e++) { p[e] = expf(l[e] - m); s += p[e]; }
    float inv = 1.f / s;
    #pragma unroll
    for (int e = 0; e < 8; e++) p[e] *= inv;
    {
        float* pr = out + PROBS_OFF + (long)tok * 8;
        *(float4*)pr       = make_float4(p[0], p[1], p[2], p[3]);
        *(float4*)(pr + 4) = make_float4(p[4], p[5], p[6], p[7]);
    }
    int e1 = 0;
    #pragma unroll
    for (int e = 1; e < 8; e++) if (p[e] > p[e1]) e1 = e;
    int e2 = (e1 == 0) ? 1 : 0;
    #pragma unroll
    for (int e = 0; e < 8; e++) if (e != e1 && p[e] > p[e2]) e2 = e;
    float d = p[e1] + p[e2] + 1e-8f;
    g_topk_e[tok * 2]     = e1;
    g_topk_e[tok * 2 + 1] = e2;
    g_topk_p[tok * 2]     = p[e1] / d;
    g_topk_p[tok * 2 + 1] = p[e2] / d;

    // deterministic psum: warp butterfly then fixed-order 4-way combine
    float w[8];
    #pragma unroll
    for (int e = 0; e < 8; e++) {
        float v = p[e];
        #pragma unroll
        for (int off = 16; off > 0; off >>= 1)
            v += __shfl_xor_sync(0xffffffffu, v, off);
        w[e] = v;
    }
    if (lane == 0) {
        #pragma unroll
        for (int e = 0; e < 8; e++) wsum[warp][e] = w[e];
    }
    __syncthreads();
    if (tid < 8)
        g_psum[blockIdx.x * 8 + tid] =
            ((wsum[0][tid] + wsum[1][tid]) + wsum[2][tid]) + wsum[3][tid];
}

// ============ k_scan: serial-order capacity scan + scatter + aux ============
__global__ void k_scan(float* __restrict__ out)
{
    __shared__ unsigned int ss[4 * 1024];
    __shared__ float psum[8];
    const int tid = threadIdx.x;

    if (tid < 8) {
        float s = 0.f;
        #pragma unroll
        for (int blk = 0; blk < 32; blk++) s += g_psum[blk * 8 + tid];
        psum[tid] = s;
    }

    int myE[8]; float myP[8];
    unsigned int c[4] = {0, 0, 0, 0};
    #pragma unroll
    for (int j = 0; j < 8; j++) {
        int n = tid * 8 + j;
        int e = g_topk_e[n];
        myE[j] = e;
        myP[j] = g_topk_p[n];
        c[e >> 1] += 1u << ((e & 1) * 16);
    }
    #pragma unroll
    for (int w = 0; w < 4; w++) ss[w * 1024 + tid] = c[w];
    __syncthreads();
    for (int off = 1; off < 1024; off <<= 1) {
        unsigned int a[4] = {0, 0, 0, 0};
        if (tid >= off) {
            #pragma unroll
            for (int w = 0; w < 4; w++) a[w] = ss[w * 1024 + tid - off];
        }
        __syncthreads();
        if (tid >= off) {
            #pragma unroll
            for (int w = 0; w < 4; w++) ss[w * 1024 + tid] += a[w];
        }
        __syncthreads();
    }
    int run[8];
    #pragma unroll
    for (int w = 0; w < 4; w++) {
        unsigned int exc = ss[w * 1024 + tid] - c[w];
        run[2 * w]     = (int)(exc & 0xffffu);
        run[2 * w + 1] = (int)(exc >> 16);
    }

    float* disp = out;
    float* comb = out + DISP_ELEMS;
    #pragma unroll
    for (int j = 0; j < 8; j++) {
        int n = tid * 8 + j;
        int e = myE[j];
        int pos = run[e]++;
        if (pos < CAP) {
            long tok = n >> 1;
            long o = tok * 12288L + (long)e * 1536L + pos;
            disp[o] = 1.0f;
            comb[o] = myP[j];
        }
    }

    if (tid == 0) {
        float aux = 0.f;
        #pragma unroll
        for (int e = 0; e < 8; e++) {
            unsigned int inc = ss[(e >> 1) * 1024 + 1023];
            float cnt = (float)((inc >> ((e & 1) * 16)) & 0xffffu);
            aux += (psum[e] * (1.f / 4096.f)) * (cnt * (1.f / 8192.f));
        }
        out[AUX_OFF] = aux * 8.f;
    }
}

// ---------------- launch ----------------
extern "C" void kernel_launch(void* const* d_in, const int* in_sizes, int n_in,
                              void* d_out, int out_size)
{
    const float* hs    = (const float*)d_in[0];
    const float* w1    = (const float*)d_in[1];
    const float* b1    = (const float*)d_in[2];
    const float* w2    = (const float*)d_in[3];
    const float* b2    = (const float*)d_in[4];
    const float* wc1   = (const float*)d_in[5];
    const float* bc1   = (const float*)d_in[6];
    const float* wc2   = (const float*)d_in[7];
    const float* bc2   = (const float*)d_in[8];
    const float* cache = (const float*)d_in[9];
    float* out = (float*)d_out;

    cudaFuncSetAttribute(k_gemm, cudaFuncAttributeMaxDynamicSharedMemorySize, DYNSMEM);

    k_prep<<<128, 256>>>(hs);
    k_split_b<<<dim3(32, 32), dim3(32, 8)>>>(w1);
    k_gemm<<<258, 256, DYNSMEM>>>(b1, w2, wc1, bc1, wc2, bc2, cache, out);
    k_final<<<32, 128>>>(b2, out);
    k_scan<<<1, 1024>>>(out);
}